// round 6
// baseline (speedup 1.0000x reference)
#include <cuda_runtime.h>
#include <cuda_bf16.h>

// out[i] = exp(-||x_i-y_i||^2) * net(x_i) * net(y_i)
// net: 9x { z = tanh(z@W^T + b)*s + t } (2->2) folded to z=tanh(Az+c), then 2->1 head.
//
// R5: MUFU was the binding pipe (37 MUFU/pair = 131k cyc floor). Offload layers
// 2 and 6 to an FMA-pipe rational tanh (Eigen coeffs, division-free Newton
// reciprocal), computed in packed f32x2 across the 2 pairs each thread holds.
// New MUFU floor: 29/pair -> ~103k cyc.

#define TPB 256
typedef unsigned long long u64;

__device__ __forceinline__ float fast_tanh(float x) {
    float y;
    asm("tanh.approx.f32 %0, %1;" : "=f"(y) : "f"(x));
    return y;
}

// ---- packed f32x2 helpers ----
__device__ __forceinline__ u64 pk(float lo, float hi) {
    u64 r; asm("mov.b64 %0, {%1, %2};" : "=l"(r) : "f"(lo), "f"(hi)); return r;
}
__device__ __forceinline__ void upk(u64 v, float& lo, float& hi) {
    asm("mov.b64 {%0, %1}, %2;" : "=f"(lo), "=f"(hi) : "l"(v));
}
__device__ __forceinline__ u64 fma2(u64 a, u64 b, u64 c) {
    u64 d; asm("fma.rn.f32x2 %0, %1, %2, %3;" : "=l"(d) : "l"(a), "l"(b), "l"(c)); return d;
}
__device__ __forceinline__ u64 mul2(u64 a, u64 b) {
    u64 d; asm("mul.rn.f32x2 %0, %1, %2;" : "=l"(d) : "l"(a), "l"(b)); return d;
}

struct TanhK {           // rational tanh coefficients, packed (c,c)
    u64 a13, a11, a9, a7, a5, a3, a1;
    u64 b6, b4, b2, b0;
    u64 two, neg1;
};

// tanh on both halves of x via x*P(x^2)/Q(x^2); reciprocal via bit-trick + 2 Newton.
// FMA/ALU pipes only (no MUFU).
__device__ __forceinline__ u64 tanh2_poly(u64 x, const TanhK& K) {
    float lo, hi;
    upk(x, lo, hi);
    lo = fminf(fmaxf(lo, -7.90531111f), 7.90531111f);
    hi = fminf(fmaxf(hi, -7.90531111f), 7.90531111f);
    u64 xc = pk(lo, hi);
    u64 x2 = mul2(xc, xc);

    u64 p = K.a13;
    p = fma2(p, x2, K.a11);
    p = fma2(p, x2, K.a9);
    p = fma2(p, x2, K.a7);
    p = fma2(p, x2, K.a5);
    p = fma2(p, x2, K.a3);
    p = fma2(p, x2, K.a1);
    u64 num = mul2(p, xc);

    u64 q = K.b6;
    q = fma2(q, x2, K.b4);
    q = fma2(q, x2, K.b2);
    q = fma2(q, x2, K.b0);

    // reciprocal of q (q > 0 always): magic-number init, 2 Newton iterations
    float qlo, qhi;
    upk(q, qlo, qhi);
    float rlo = __int_as_float(0x7EF311C3 - __float_as_int(qlo));
    float rhi = __int_as_float(0x7EF311C3 - __float_as_int(qhi));
    u64 r = pk(rlo, rhi);
    u64 nq = mul2(q, K.neg1);
    r = mul2(r, fma2(nq, r, K.two));
    r = mul2(r, fma2(nq, r, K.two));

    return mul2(num, r);
}

// scalar fallback for a single tail pair (all-MUFU path)
__device__ __noinline__ float one_pair(const u64* sW2, const u64* sC2, const u64* sF2,
                                       float2 xv, float2 yv)
{
    float dx = xv.x - yv.x, dy = xv.y - yv.y;
    float rbf = __expf(-fmaf(dx, dx, dy * dy));
    float a0 = xv.x, a1 = xv.y, b0 = yv.x, b1 = yv.y;
    #pragma unroll 1
    for (int l = 0; l < 9; l++) {
        float w00, w01, w10, w11, c0, c1, junk;
        upk(sW2[l*4+0], w00, junk); upk(sW2[l*4+1], w01, junk);
        upk(sW2[l*4+2], w10, junk); upk(sW2[l*4+3], w11, junk);
        upk(sC2[l*2+0], c0, junk);  upk(sC2[l*2+1], c1, junk);
        float u0 = fmaf(a0, w00, fmaf(a1, w01, c0));
        float u1 = fmaf(a0, w10, fmaf(a1, w11, c1));
        float v0 = fmaf(b0, w00, fmaf(b1, w01, c0));
        float v1 = fmaf(b0, w10, fmaf(b1, w11, c1));
        a0 = fast_tanh(u0); a1 = fast_tanh(u1);
        b0 = fast_tanh(v0); b1 = fast_tanh(v1);
    }
    float f0, f1, fb, junk;
    upk(sF2[0], f0, junk); upk(sF2[1], f1, junk); upk(sF2[2], fb, junk);
    float fx = fmaf(a0, f0, fmaf(a1, f1, fb));
    float fy = fmaf(b0, f0, fmaf(b1, f1, fb));
    return rbf * fx * fy;
}

__global__ __launch_bounds__(TPB, 3)
void fraud_kernel(const float4* __restrict__ x4,
                  const float4* __restrict__ y4,
                  const float* __restrict__ W0,
                  const float* __restrict__ b0,
                  const float* __restrict__ scale0,
                  const float* __restrict__ shift0,
                  const float* __restrict__ Ws,
                  const float* __restrict__ bs,
                  const float* __restrict__ scales,
                  const float* __restrict__ shifts,
                  const float* __restrict__ Wf,
                  const float* __restrict__ bf,
                  float* __restrict__ out,
                  int n)
{
    __shared__ u64 sW2[9 * 4];   // folded weights, duplicated halves (w,w)
    __shared__ u64 sC2[9 * 2];   // folded biases
    __shared__ u64 sF2[3];       // folded head

    const int tid = threadIdx.x;

    // ---- fold scale/shift of layer l-1 into layer l (done by 10 threads) ----
    if (tid < 9) {
        const float* W = (tid == 0) ? W0 : (Ws + (tid - 1) * 4);
        const float* B = (tid == 0) ? b0 : (bs + (tid - 1) * 2);
        float ps0 = 1.f, ps1 = 1.f, pt0 = 0.f, pt1 = 0.f;
        if (tid == 1) {
            ps0 = scale0[0]; ps1 = scale0[1];
            pt0 = shift0[0]; pt1 = shift0[1];
        } else if (tid >= 2) {
            ps0 = scales[(tid - 2) * 2 + 0]; ps1 = scales[(tid - 2) * 2 + 1];
            pt0 = shifts[(tid - 2) * 2 + 0]; pt1 = shifts[(tid - 2) * 2 + 1];
        }
        float w00 = W[0] * ps0, w01 = W[1] * ps1;
        float w10 = W[2] * ps0, w11 = W[3] * ps1;
        float c0 = B[0] + W[0] * pt0 + W[1] * pt1;
        float c1 = B[1] + W[2] * pt0 + W[3] * pt1;
        sW2[tid * 4 + 0] = pk(w00, w00);
        sW2[tid * 4 + 1] = pk(w01, w01);
        sW2[tid * 4 + 2] = pk(w10, w10);
        sW2[tid * 4 + 3] = pk(w11, w11);
        sC2[tid * 2 + 0] = pk(c0, c0);
        sC2[tid * 2 + 1] = pk(c1, c1);
    } else if (tid == 9) {
        float s0 = scales[14], s1 = scales[15];
        float t0 = shifts[14], t1 = shifts[15];
        float f0 = Wf[0] * s0, f1 = Wf[1] * s1;
        float fb = bf[0] + Wf[0] * t0 + Wf[1] * t1;
        sF2[0] = pk(f0, f0);
        sF2[1] = pk(f1, f1);
        sF2[2] = pk(fb, fb);
    }
    __syncthreads();

    // rational-tanh coefficients (Eigen f32 tanh), packed
    TanhK K;
    K.a13 = pk(-2.76076847742355e-16f, -2.76076847742355e-16f);
    K.a11 = pk( 2.00018790482477e-13f,  2.00018790482477e-13f);
    K.a9  = pk(-8.60467152213735e-11f, -8.60467152213735e-11f);
    K.a7  = pk( 5.12229709037114e-08f,  5.12229709037114e-08f);
    K.a5  = pk( 1.48572235717979e-05f,  1.48572235717979e-05f);
    K.a3  = pk( 6.37261928875436e-04f,  6.37261928875436e-04f);
    K.a1  = pk( 4.89352455891786e-03f,  4.89352455891786e-03f);
    K.b6  = pk( 1.19825839466702e-06f,  1.19825839466702e-06f);
    K.b4  = pk( 1.18534705686654e-04f,  1.18534705686654e-04f);
    K.b2  = pk( 2.26843463243900e-03f,  2.26843463243900e-03f);
    K.b0  = pk( 4.89352518554385e-03f,  4.89352518554385e-03f);
    K.two = pk(2.0f, 2.0f);
    K.neg1 = pk(-1.0f, -1.0f);

    #pragma unroll
    for (int g = 0; g < 2; g++) {
        int f = blockIdx.x * (TPB * 2) + g * TPB + tid;  // float4 index (2 pairs)
        int p0 = 2 * f;
        if (p0 + 1 < n) {
            float4 xa = x4[f];
            float4 ya = y4[f];

            // RBF (scalar; 2 EX2)
            float dxA = xa.x - ya.x, dyA = xa.y - ya.y;
            float dxB = xa.z - ya.z, dyB = xa.w - ya.w;
            float rbfA = __expf(-fmaf(dxA, dxA, dyA * dyA));
            float rbfB = __expf(-fmaf(dxB, dxB, dyB * dyB));

            // packed state: halves = (pair A, pair B)
            u64 zx0 = pk(xa.x, xa.z), zx1 = pk(xa.y, xa.w);   // net(x)
            u64 zy0 = pk(ya.x, ya.z), zy1 = pk(ya.y, ya.w);   // net(y)

            #pragma unroll 1
            for (int l = 0; l < 9; l++) {
                const u64 w00 = sW2[l*4+0], w01 = sW2[l*4+1];
                const u64 w10 = sW2[l*4+2], w11 = sW2[l*4+3];
                const u64 e0 = sC2[l*2+0], e1 = sC2[l*2+1];

                u64 ux0 = fma2(zx0, w00, fma2(zx1, w01, e0));
                u64 ux1 = fma2(zx0, w10, fma2(zx1, w11, e1));
                u64 uy0 = fma2(zy0, w00, fma2(zy1, w01, e0));
                u64 uy1 = fma2(zy0, w10, fma2(zy1, w11, e1));

                if (l == 2 || l == 6) {
                    // FMA-pipe rational tanh (no MUFU)
                    zx0 = tanh2_poly(ux0, K);
                    zx1 = tanh2_poly(ux1, K);
                    zy0 = tanh2_poly(uy0, K);
                    zy1 = tanh2_poly(uy1, K);
                } else {
                    float t0, t1, t2, t3, t4, t5, t6, t7;
                    upk(ux0, t0, t1); upk(ux1, t2, t3);
                    upk(uy0, t4, t5); upk(uy1, t6, t7);
                    t0 = fast_tanh(t0); t1 = fast_tanh(t1);
                    t2 = fast_tanh(t2); t3 = fast_tanh(t3);
                    t4 = fast_tanh(t4); t5 = fast_tanh(t5);
                    t6 = fast_tanh(t6); t7 = fast_tanh(t7);
                    zx0 = pk(t0, t1); zx1 = pk(t2, t3);
                    zy0 = pk(t4, t5); zy1 = pk(t6, t7);
                }
            }

            u64 fx = fma2(zx0, sF2[0], fma2(zx1, sF2[1], sF2[2]));
            u64 fy = fma2(zy0, sF2[0], fma2(zy1, sF2[1], sF2[2]));
            u64 prod = mul2(fx, fy);
            u64 res = mul2(prod, pk(rbfA, rbfB));

            float rA, rB;
            upk(res, rA, rB);
            float2 r2; r2.x = rA; r2.y = rB;
            reinterpret_cast<float2*>(out)[f] = r2;
        } else if (p0 < n) {
            const float2* x2p = reinterpret_cast<const float2*>(x4);
            const float2* y2p = reinterpret_cast<const float2*>(y4);
            out[p0] = one_pair(sW2, sC2, sF2, x2p[p0], y2p[p0]);
        }
    }
}

extern "C" void kernel_launch(void* const* d_in, const int* in_sizes, int n_in,
                              void* d_out, int out_size)
{
    const float4* x4     = (const float4*)d_in[0];
    const float4* y4     = (const float4*)d_in[1];
    const float*  W0     = (const float*)d_in[2];
    const float*  b0     = (const float*)d_in[3];
    const float*  scale0 = (const float*)d_in[4];
    const float*  shift0 = (const float*)d_in[5];
    const float*  Ws     = (const float*)d_in[6];
    const float*  bs     = (const float*)d_in[7];
    const float*  scales = (const float*)d_in[8];
    const float*  shifts = (const float*)d_in[9];
    const float*  Wf     = (const float*)d_in[10];
    const float*  bf     = (const float*)d_in[11];
    float* out = (float*)d_out;

    int n = in_sizes[0] / 2;            // pairs
    int per_block = TPB * 4;            // 4 pairs per thread
    int blocks = (n + per_block - 1) / per_block;

    fraud_kernel<<<blocks, TPB>>>(x4, y4, W0, b0, scale0, shift0,
                                  Ws, bs, scales, shifts, Wf, bf, out, n);
}

// round 7
// speedup vs baseline: 1.0643x; 1.0643x over previous
#include <cuda_runtime.h>
#include <cuda_bf16.h>

// out[i] = exp(-||x_i-y_i||^2) * net(x_i) * net(y_i)
// net: 9x { z = tanh(z@W^T + b)*s + t } (2->2) folded to z = tanh(Az+c), head 2->1.
//
// R7: R4 structure (MUFU-bound at 37 MUFU/pair). Offload ONE layer's tanh (4/pair)
// to a scalar FMA-pipe rational tanh -> MUFU 33/pair. Params in smem as float4
// (2x LDS.128/layer). Occupancy kept at 4 CTAs/SM.

#define TPB 256

__device__ __forceinline__ float fast_tanh(float x) {
    float y;
    asm("tanh.approx.f32 %0, %1;" : "=f"(y) : "f"(x));
    return y;
}

// FMA/ALU-pipe tanh: Eigen 13/6 rational, reciprocal via bit-trick + 2 Newton.
__device__ __forceinline__ float tanh_poly(float x) {
    x = fminf(fmaxf(x, -7.90531111f), 7.90531111f);
    float x2 = x * x;
    float p = -2.76076847742355e-16f;
    p = fmaf(p, x2, 2.00018790482477e-13f);
    p = fmaf(p, x2, -8.60467152213735e-11f);
    p = fmaf(p, x2, 5.12229709037114e-08f);
    p = fmaf(p, x2, 1.48572235717979e-05f);
    p = fmaf(p, x2, 6.37261928875436e-04f);
    p = fmaf(p, x2, 4.89352455891786e-03f);
    float num = p * x;
    float q = 1.19825839466702e-06f;
    q = fmaf(q, x2, 1.18534705686654e-04f);
    q = fmaf(q, x2, 2.26843463243900e-03f);
    q = fmaf(q, x2, 4.89352518554385e-03f);
    // 1/q, q in [0.0049, ~0.91]: magic init + 2 Newton (all FMA pipe)
    float r = __int_as_float(0x7EF311C3 - __float_as_int(q));
    r = r * fmaf(-q, r, 2.0f);
    r = r * fmaf(-q, r, 2.0f);
    return num * r;
}

// tail fallback: single pair, all-MUFU
__device__ __noinline__ float one_pair(const float4* sW4, const float4* sC4,
                                       float4 hF, float2 xv, float2 yv)
{
    float dx = xv.x - yv.x, dy = xv.y - yv.y;
    float rbf = __expf(-fmaf(dx, dx, dy * dy));
    float a0 = xv.x, a1 = xv.y, b0 = yv.x, b1 = yv.y;
    #pragma unroll 1
    for (int l = 0; l < 9; l++) {
        float4 W = sW4[l];
        float4 C = sC4[l];
        float u0 = fmaf(a0, W.x, fmaf(a1, W.y, C.x));
        float u1 = fmaf(a0, W.z, fmaf(a1, W.w, C.y));
        float v0 = fmaf(b0, W.x, fmaf(b1, W.y, C.x));
        float v1 = fmaf(b0, W.z, fmaf(b1, W.w, C.y));
        a0 = fast_tanh(u0); a1 = fast_tanh(u1);
        b0 = fast_tanh(v0); b1 = fast_tanh(v1);
    }
    float fx = fmaf(a0, hF.x, fmaf(a1, hF.y, hF.z));
    float fy = fmaf(b0, hF.x, fmaf(b1, hF.y, hF.z));
    return rbf * fx * fy;
}

// one MUFU layer step for 8 chains (2 pairs x 2 nets x 2 units)
#define LAYER_MUFU(W, C)                                                   \
    {                                                                      \
        float ua0 = fmaf(a0,  (W).x, fmaf(a1,  (W).y, (C).x));             \
        float ua1 = fmaf(a0,  (W).z, fmaf(a1,  (W).w, (C).y));             \
        float ub0 = fmaf(b0_, (W).x, fmaf(b1_, (W).y, (C).x));             \
        float ub1 = fmaf(b0_, (W).z, fmaf(b1_, (W).w, (C).y));             \
        float uc0 = fmaf(c0,  (W).x, fmaf(c1,  (W).y, (C).x));             \
        float uc1 = fmaf(c0,  (W).z, fmaf(c1,  (W).w, (C).y));             \
        float ud0 = fmaf(d0,  (W).x, fmaf(d1,  (W).y, (C).x));             \
        float ud1 = fmaf(d0,  (W).z, fmaf(d1,  (W).w, (C).y));             \
        a0  = fast_tanh(ua0); a1  = fast_tanh(ua1);                        \
        b0_ = fast_tanh(ub0); b1_ = fast_tanh(ub1);                        \
        c0  = fast_tanh(uc0); c1  = fast_tanh(uc1);                        \
        d0  = fast_tanh(ud0); d1  = fast_tanh(ud1);                        \
    }

__global__ __launch_bounds__(TPB, 4)
void fraud_kernel(const float4* __restrict__ x4,
                  const float4* __restrict__ y4,
                  const float* __restrict__ W0,
                  const float* __restrict__ b0,
                  const float* __restrict__ scale0,
                  const float* __restrict__ shift0,
                  const float* __restrict__ Ws,
                  const float* __restrict__ bs,
                  const float* __restrict__ scales,
                  const float* __restrict__ shifts,
                  const float* __restrict__ Wf,
                  const float* __restrict__ bf,
                  float* __restrict__ out,
                  int n)
{
    __shared__ float4 sW4[9];   // folded weights (w00,w01,w10,w11)
    __shared__ float4 sC4[9];   // folded biases  (c0,c1,-,-)
    __shared__ float4 sF4;      // folded head    (f0,f1,fb,-)

    const int tid = threadIdx.x;

    // fold scale/shift of layer l-1 into layer l's (W,b); head folds layer 8's
    if (tid < 9) {
        const float* W = (tid == 0) ? W0 : (Ws + (tid - 1) * 4);
        const float* B = (tid == 0) ? b0 : (bs + (tid - 1) * 2);
        float ps0 = 1.f, ps1 = 1.f, pt0 = 0.f, pt1 = 0.f;
        if (tid == 1) {
            ps0 = scale0[0]; ps1 = scale0[1];
            pt0 = shift0[0]; pt1 = shift0[1];
        } else if (tid >= 2) {
            ps0 = scales[(tid - 2) * 2 + 0]; ps1 = scales[(tid - 2) * 2 + 1];
            pt0 = shifts[(tid - 2) * 2 + 0]; pt1 = shifts[(tid - 2) * 2 + 1];
        }
        float4 w;
        w.x = W[0] * ps0; w.y = W[1] * ps1;
        w.z = W[2] * ps0; w.w = W[3] * ps1;
        sW4[tid] = w;
        float4 c;
        c.x = B[0] + W[0] * pt0 + W[1] * pt1;
        c.y = B[1] + W[2] * pt0 + W[3] * pt1;
        c.z = 0.f; c.w = 0.f;
        sC4[tid] = c;
    } else if (tid == 9) {
        float s0 = scales[14], s1 = scales[15];
        float t0 = shifts[14], t1 = shifts[15];
        float4 f;
        f.x = Wf[0] * s0;
        f.y = Wf[1] * s1;
        f.z = bf[0] + Wf[0] * t0 + Wf[1] * t1;
        f.w = 0.f;
        sF4 = f;
    }
    __syncthreads();

    #pragma unroll
    for (int g = 0; g < 2; g++) {
        int f = blockIdx.x * (TPB * 2) + g * TPB + tid;  // float4 index = 2 pairs
        int p0 = 2 * f;
        if (p0 + 1 < n) {
            float4 xa = x4[f];
            float4 ya = y4[f];

            float dxA = xa.x - ya.x, dyA = xa.y - ya.y;
            float dxB = xa.z - ya.z, dyB = xa.w - ya.w;
            float rbfA = __expf(-fmaf(dxA, dxA, dyA * dyA));
            float rbfB = __expf(-fmaf(dxB, dxB, dyB * dyB));

            float a0 = xa.x, a1 = xa.y;    // net(x_A)
            float b0_ = ya.x, b1_ = ya.y;  // net(y_A)
            float c0 = xa.z, c1 = xa.w;    // net(x_B)
            float d0 = ya.z, d1 = ya.w;    // net(y_B)

            // layers 0..3 on MUFU
            #pragma unroll 1
            for (int l = 0; l < 4; l++) {
                float4 W = sW4[l];
                float4 C = sC4[l];
                LAYER_MUFU(W, C);
            }

            // layer 4 on FMA pipe (poly tanh)
            {
                float4 W = sW4[4];
                float4 C = sC4[4];
                float ua0 = fmaf(a0,  W.x, fmaf(a1,  W.y, C.x));
                float ua1 = fmaf(a0,  W.z, fmaf(a1,  W.w, C.y));
                float ub0 = fmaf(b0_, W.x, fmaf(b1_, W.y, C.x));
                float ub1 = fmaf(b0_, W.z, fmaf(b1_, W.w, C.y));
                float uc0 = fmaf(c0,  W.x, fmaf(c1,  W.y, C.x));
                float uc1 = fmaf(c0,  W.z, fmaf(c1,  W.w, C.y));
                float ud0 = fmaf(d0,  W.x, fmaf(d1,  W.y, C.x));
                float ud1 = fmaf(d0,  W.z, fmaf(d1,  W.w, C.y));
                a0  = tanh_poly(ua0); a1  = tanh_poly(ua1);
                b0_ = tanh_poly(ub0); b1_ = tanh_poly(ub1);
                c0  = tanh_poly(uc0); c1  = tanh_poly(uc1);
                d0  = tanh_poly(ud0); d1  = tanh_poly(ud1);
            }

            // layers 5..8 on MUFU
            #pragma unroll 1
            for (int l = 5; l < 9; l++) {
                float4 W = sW4[l];
                float4 C = sC4[l];
                LAYER_MUFU(W, C);
            }

            float4 F = sF4;
            float fxA = fmaf(a0,  F.x, fmaf(a1,  F.y, F.z));
            float fyA = fmaf(b0_, F.x, fmaf(b1_, F.y, F.z));
            float fxB = fmaf(c0,  F.x, fmaf(c1,  F.y, F.z));
            float fyB = fmaf(d0,  F.x, fmaf(d1,  F.y, F.z));

            float2 r;
            r.x = rbfA * fxA * fyA;
            r.y = rbfB * fxB * fyB;
            reinterpret_cast<float2*>(out)[f] = r;
        } else if (p0 < n) {
            const float2* x2p = reinterpret_cast<const float2*>(x4);
            const float2* y2p = reinterpret_cast<const float2*>(y4);
            out[p0] = one_pair(sW4, sC4, sF4, x2p[p0], y2p[p0]);
        }
    }
}

extern "C" void kernel_launch(void* const* d_in, const int* in_sizes, int n_in,
                              void* d_out, int out_size)
{
    const float4* x4     = (const float4*)d_in[0];
    const float4* y4     = (const float4*)d_in[1];
    const float*  W0     = (const float*)d_in[2];
    const float*  b0     = (const float*)d_in[3];
    const float*  scale0 = (const float*)d_in[4];
    const float*  shift0 = (const float*)d_in[5];
    const float*  Ws     = (const float*)d_in[6];
    const float*  bs     = (const float*)d_in[7];
    const float*  scales = (const float*)d_in[8];
    const float*  shifts = (const float*)d_in[9];
    const float*  Wf     = (const float*)d_in[10];
    const float*  bf     = (const float*)d_in[11];
    float* out = (float*)d_out;

    int n = in_sizes[0] / 2;            // pairs
    int per_block = TPB * 4;            // 4 pairs per thread
    int blocks = (n + per_block - 1) / per_block;

    fraud_kernel<<<blocks, TPB>>>(x4, y4, W0, b0, scale0, shift0,
                                  Ws, bs, scales, shifts, Wf, bf, out, n);
}